// round 1
// baseline (speedup 1.0000x reference)
#include <cuda_runtime.h>

// Problem constants (shapes fixed by the dataset; N and B taken at runtime).
#define THREADS 256
#define MAXN    128      // max cached nodes per segment (mean 61, max ~95)
#define DDIM    128
#define NHEAD   4

// Shared memory layout (floats):
//  sW [NHEAD*DDIM] | xs [MAXN*DDIM] | sc [MAXN*NHEAD] | cw [MAXN] | red [32] | pool2 [DDIM]
#define SMEM_FLOATS (NHEAD*DDIM + MAXN*DDIM + MAXN*NHEAD + MAXN + 32 + DDIM)
#define SMEM_BYTES  (SMEM_FLOATS * sizeof(float))

// Scratch for segment boundaries (device global: no allocations allowed).
__device__ int g_seg[65538];

__device__ __forceinline__ long long get_id(const void* ids, int i, bool is64) {
    if (is64) return ((const long long*)ids)[i];
    return (long long)((const int*)ids)[i];
}

// Kernel A: per-segment start offsets via lower_bound on the sorted ids.
// Also detects int64 vs int32 storage: for sorted small int64 values, the
// odd-indexed int32 words near the tail are all high-words == 0; for int32
// data the tail values are ~B-1 != 0.
__global__ void seg_bounds_kernel(const void* __restrict__ ids, int N, int B) {
    const int* w = (const int*)ids;
    bool is64 = false;
    if (N >= 8) {
        int nz = 0;
        #pragma unroll
        for (int k = 1; k <= 7; k += 2) nz += (w[N - k] != 0);
        is64 = (nz == 0);
    }
    int b = blockIdx.x * blockDim.x + threadIdx.x;
    if (b > B) return;
    int lo = 0, hi = N;
    while (lo < hi) {
        int mid = (lo + hi) >> 1;
        if (get_id(ids, mid, is64) < (long long)b) lo = mid + 1;
        else hi = mid;
    }
    g_seg[b] = lo;
}

// 4-wide block reduction (max or sum) across 256 threads / 8 warps.
__device__ __forceinline__ void block_reduce4(float v[NHEAD], float* red,
                                              float* out, bool do_max) {
    const int lane = threadIdx.x & 31;
    const int warp = threadIdx.x >> 5;
    #pragma unroll
    for (int off = 16; off > 0; off >>= 1) {
        #pragma unroll
        for (int h = 0; h < NHEAD; h++) {
            float o = __shfl_down_sync(0xffffffffu, v[h], off);
            v[h] = do_max ? fmaxf(v[h], o) : (v[h] + o);
        }
    }
    if (lane == 0) {
        #pragma unroll
        for (int h = 0; h < NHEAD; h++) red[warp * NHEAD + h] = v[h];
    }
    __syncthreads();
    if (threadIdx.x < NHEAD) {
        float r = red[threadIdx.x];
        #pragma unroll
        for (int w2 = 1; w2 < THREADS / 32; w2++) {
            float o = red[w2 * NHEAD + threadIdx.x];
            r = do_max ? fmaxf(r, o) : (r + o);
        }
        out[threadIdx.x] = r;
    }
    __syncthreads();
}

// Scalar per-row score (fallback path only).
__device__ __forceinline__ void score_row(const float* __restrict__ xr,
                                          const float* __restrict__ sW,
                                          float sv[NHEAD]) {
    #pragma unroll
    for (int h = 0; h < NHEAD; h++) sv[h] = 0.f;
    for (int d = 0; d < DDIM; d++) {
        float xv = xr[d];
        #pragma unroll
        for (int h = 0; h < NHEAD; h++) sv[h] = fmaf(xv, sW[h * DDIM + d], sv[h]);
    }
}

__global__ __launch_bounds__(THREADS, 3)
void attn_pool_kernel(const float* __restrict__ x,
                      const float* __restrict__ W,
                      const float* __restrict__ bias,
                      const float* __restrict__ temp,
                      float* __restrict__ out_pool,
                      float* __restrict__ out_attn,
                      int N) {
    const int b    = blockIdx.x;
    const int t    = threadIdx.x;
    const int lane = t & 31;
    const int warp = t >> 5;

    extern __shared__ float sm[];
    float* sW    = sm;                        // NHEAD*DDIM
    float* xs    = sW + NHEAD * DDIM;         // MAXN*DDIM
    float* sc    = xs + MAXN * DDIM;          // MAXN*NHEAD
    float* cw    = sc + MAXN * NHEAD;         // MAXN
    float* red   = cw + MAXN;                 // 32
    float* pool2 = red + 32;                  // DDIM

    __shared__ float sb[NHEAD];
    __shared__ float smax[NHEAD], sinv[NHEAD];
    __shared__ float sInvT;

    for (int i = t; i < NHEAD * DDIM; i += THREADS) sW[i] = W[i];
    if (t < NHEAD) sb[t] = bias[t];
    if (t == 0)   sInvT = 1.0f / temp[0];
    __syncthreads();
    const float invT = sInvT;

    const int g0  = g_seg[b];
    const int cnt = g_seg[b + 1] - g0;

    if (cnt == 0) {
        if (t < DDIM) out_pool[(size_t)b * DDIM + t] = 0.0f;
        return;
    }

    if (cnt <= MAXN) {
        // ---- Phase 1: stream x rows into smem (warp per node, f32x4 rows) ----
        for (int n = warp; n < cnt; n += THREADS / 32) {
            const float4 v = ((const float4*)(x + (size_t)(g0 + n) * DDIM))[lane];
            ((float4*)(xs + n * DDIM))[lane] = v;
        }
        __syncthreads();

        // ---- Phase 2: per-node head scores from smem (warp per node) ----
        for (int n = warp; n < cnt; n += THREADS / 32) {
            const float4 v = ((const float4*)(xs + n * DDIM))[lane];
            float p[NHEAD];
            #pragma unroll
            for (int h = 0; h < NHEAD; h++) {
                const float* wr = sW + h * DDIM + lane * 4;
                p[h] = v.x * wr[0] + v.y * wr[1] + v.z * wr[2] + v.w * wr[3];
            }
            #pragma unroll
            for (int off = 16; off > 0; off >>= 1) {
                #pragma unroll
                for (int h = 0; h < NHEAD; h++)
                    p[h] += __shfl_down_sync(0xffffffffu, p[h], off);
            }
            if (lane == 0) {
                #pragma unroll
                for (int h = 0; h < NHEAD; h++)
                    sc[n * NHEAD + h] = (p[h] + sb[h]) * invT;
            }
        }
        __syncthreads();

        // ---- Phase 3: segment softmax (thread t <-> node t; cnt <= 128) ----
        float m[NHEAD];
        #pragma unroll
        for (int h = 0; h < NHEAD; h++)
            m[h] = (t < cnt) ? sc[t * NHEAD + h] : -3.4e38f;
        block_reduce4(m, red, smax, true);

        float e[NHEAD], s[NHEAD];
        #pragma unroll
        for (int h = 0; h < NHEAD; h++) {
            e[h] = (t < cnt) ? expf(sc[t * NHEAD + h] - smax[h]) : 0.f;
            s[h] = e[h];
        }
        block_reduce4(s, red, sinv, false);
        if (t < NHEAD) sinv[t] = 1.0f / sinv[t];
        __syncthreads();

        // ---- Phase 4: attention write (coalesced per head) + node weights ----
        if (t < cnt) {
            float c = 0.f;
            #pragma unroll
            for (int h = 0; h < NHEAD; h++) {
                float a = e[h] * sinv[h];
                out_attn[(size_t)h * N + g0 + t] = a;
                c += a;
            }
            cw[t] = c * (1.0f / NHEAD);
        }
        __syncthreads();

        // ---- Phase 5: weighted row-sum pooling from smem ----
        const int half = (cnt + 1) >> 1;
        const int d    = t & (DDIM - 1);
        const int n0   = (t < DDIM) ? 0 : half;
        const int n1   = (t < DDIM) ? half : cnt;
        float acc = 0.f;
        for (int n = n0; n < n1; n++)
            acc = fmaf(cw[n], xs[n * DDIM + d], acc);
        if (t >= DDIM) pool2[d] = acc;
        __syncthreads();
        if (t < DDIM) out_pool[(size_t)b * DDIM + d] = acc + pool2[d];

    } else {
        // ---- Fallback (cnt > MAXN, probability ~1e-10): stream + recompute ----
        float m[NHEAD];
        #pragma unroll
        for (int h = 0; h < NHEAD; h++) m[h] = -3.4e38f;
        for (int n = t; n < cnt; n += THREADS) {
            float sv[NHEAD];
            score_row(x + (size_t)(g0 + n) * DDIM, sW, sv);
            #pragma unroll
            for (int h = 0; h < NHEAD; h++)
                m[h] = fmaxf(m[h], (sv[h] + sb[h]) * invT);
        }
        block_reduce4(m, red, smax, true);

        float s[NHEAD];
        #pragma unroll
        for (int h = 0; h < NHEAD; h++) s[h] = 0.f;
        for (int n = t; n < cnt; n += THREADS) {
            float sv[NHEAD];
            score_row(x + (size_t)(g0 + n) * DDIM, sW, sv);
            #pragma unroll
            for (int h = 0; h < NHEAD; h++)
                s[h] += expf((sv[h] + sb[h]) * invT - smax[h]);
        }
        block_reduce4(s, red, sinv, false);
        if (t < NHEAD) sinv[t] = 1.0f / sinv[t];
        if (t < DDIM) xs[t] = 0.f;   // reuse xs[0..DDIM) as pool accumulator
        __syncthreads();

        for (int n = t; n < cnt; n += THREADS) {
            const float* xr = x + (size_t)(g0 + n) * DDIM;
            float sv[NHEAD];
            score_row(xr, sW, sv);
            float c = 0.f;
            #pragma unroll
            for (int h = 0; h < NHEAD; h++) {
                float a = expf((sv[h] + sb[h]) * invT - smax[h]) * sinv[h];
                out_attn[(size_t)h * N + g0 + n] = a;
                c += a;
            }
            c *= (1.0f / NHEAD);
            for (int d2 = 0; d2 < DDIM; d2++)
                atomicAdd(&xs[d2], c * xr[d2]);
        }
        __syncthreads();
        if (t < DDIM) out_pool[(size_t)b * DDIM + t] = xs[t];
    }
}

extern "C" void kernel_launch(void* const* d_in, const int* in_sizes, int n_in,
                              void* d_out, int out_size) {
    // Inputs (metadata order): x [N,D] f32, batch_indices [N] int, W [H,D] f32,
    //                          b [H] f32, temperature [] f32
    const float* x    = (const float*)d_in[0];
    const void*  ids  = d_in[1];
    const float* W    = (const float*)d_in[2];
    const float* bias = (const float*)d_in[3];
    const float* temp = (const float*)d_in[4];

    const int N = in_sizes[1];
    const int B = (out_size - NHEAD * N) / DDIM;   // out = [B*D pooled | H*N attn]

    cudaFuncSetAttribute(attn_pool_kernel,
                         cudaFuncAttributeMaxDynamicSharedMemorySize,
                         (int)SMEM_BYTES);

    seg_bounds_kernel<<<(B + 1 + 255) / 256, 256>>>(ids, N, B);

    float* out_pool = (float*)d_out;
    float* out_attn = out_pool + (size_t)B * DDIM;
    attn_pool_kernel<<<B, THREADS, SMEM_BYTES>>>(x, W, bias, temp,
                                                 out_pool, out_attn, N);
}

// round 4
// speedup vs baseline: 1.4307x; 1.4307x over previous
#include <cuda_runtime.h>
#include <cfloat>

#define DDIM   128
#define NHEAD  4
#define WPB    8            // warps per CTA
#define THREADS (WPB * 32)
#define MAXW   192          // score slots per warp (max cnt ~100 expected)

// Scratch for segment boundaries (device global: no allocations allowed).
__device__ int g_seg[65538];

__device__ __forceinline__ long long get_id(const void* ids, int i, bool is64) {
    if (is64) return ((const long long*)ids)[i];
    return (long long)((const int*)ids)[i];
}

// Kernel A: per-segment start offsets via lower_bound on sorted ids.
// Detects int64 vs int32 storage (sorted small int64 -> odd words at tail are 0).
__global__ void seg_bounds_kernel(const void* __restrict__ ids, int N, int B) {
    const int* w = (const int*)ids;
    bool is64 = false;
    if (N >= 8) {
        int nz = 0;
        #pragma unroll
        for (int k = 1; k <= 7; k += 2) nz += (w[N - k] != 0);
        is64 = (nz == 0);
    }
    int b = blockIdx.x * blockDim.x + threadIdx.x;
    if (b > B) return;
    int lo = 0, hi = N;
    while (lo < hi) {
        int mid = (lo + hi) >> 1;
        if (get_id(ids, mid, is64) < (long long)b) lo = mid + 1;
        else hi = mid;
    }
    g_seg[b] = lo;
}

// Warp-cooperative 4-head score for one row (float4 per lane).
// Returns s[0..3] on ALL lanes. 11 SHFL + 11 FADD + 4 SHFL-bcast.
__device__ __forceinline__ void warp_scores(
    float4 v, const float4 w[NHEAD], const float bini[NHEAD],
    int lane, float s[NHEAD]) {
    float p[NHEAD];
    #pragma unroll
    for (int h = 0; h < NHEAD; h++) {
        float t = fmaf(v.x, w[h].x, bini[h]);
        t = fmaf(v.y, w[h].y, t);
        t = fmaf(v.z, w[h].z, t);
        p[h] = fmaf(v.w, w[h].w, t);
    }
    // reduce over lane bits 4,3 for all 4 heads
    #pragma unroll
    for (int m = 16; m >= 8; m >>= 1) {
        #pragma unroll
        for (int h = 0; h < NHEAD; h++)
            p[h] += __shfl_xor_sync(0xffffffffu, p[h], m);
    }
    // transpose: lane group g = lane>>3 takes head g, reduce remaining 8 lanes
    int g = lane >> 3;
    float v8 = (g < 2) ? ((g == 0) ? p[0] : p[1]) : ((g == 2) ? p[2] : p[3]);
    #pragma unroll
    for (int m = 4; m >= 1; m >>= 1)
        v8 += __shfl_xor_sync(0xffffffffu, v8, m);
    #pragma unroll
    for (int h = 0; h < NHEAD; h++)
        s[h] = __shfl_sync(0xffffffffu, v8, h * 8);
}

__global__ __launch_bounds__(THREADS, 3)
void attn_pool_warp_kernel(const float* __restrict__ x,
                           const float* __restrict__ W,
                           const float* __restrict__ bias,
                           const float* __restrict__ temp,
                           float* __restrict__ out_pool,
                           float* __restrict__ out_attn,
                           int N, int B) {
    const int lane = threadIdx.x & 31;
    const int warp = threadIdx.x >> 5;
    const int b    = blockIdx.x * WPB + warp;

    __shared__ float4 ssc[WPB][MAXW];   // per-warp score slots

    if (b >= B) return;

    const float invT = 1.0f / temp[0];

    // Per-lane weights (folded with 1/T); bias distributed over 32 lane partials.
    float4 w[NHEAD];
    float  bini[NHEAD];
    #pragma unroll
    for (int h = 0; h < NHEAD; h++) {
        const float4 wr = ((const float4*)(W + h * DDIM))[lane];
        w[h] = make_float4(wr.x * invT, wr.y * invT, wr.z * invT, wr.w * invT);
        bini[h] = bias[h] * invT * (1.0f / 32.0f);
    }

    const int g0  = g_seg[b];
    const int cnt = g_seg[b + 1] - g0;

    if (cnt == 0) {
        ((float4*)(out_pool + (size_t)b * DDIM))[lane] =
            make_float4(0.f, 0.f, 0.f, 0.f);
        return;
    }

    // ---- Pass A: single sweep over x -- scores + online softmax + pooling ----
    float m[NHEAD], S[NHEAD];
    float4 acc[NHEAD];
    #pragma unroll
    for (int h = 0; h < NHEAD; h++) {
        m[h] = -FLT_MAX; S[h] = 0.f;
        acc[h] = make_float4(0.f, 0.f, 0.f, 0.f);
    }

    const float4* xrow = (const float4*)(x + (size_t)g0 * DDIM);
    float4 v = xrow[lane];                        // prefetch row 0

    for (int n = 0; n < cnt; n++) {
        // Unconditional prefetch of next row (clamped index) keeps the LDG
        // hoisted/unpredicated -> 2 rows in flight.
        const int np = (n + 1 < cnt) ? (n + 1) : n;
        float4 vn = xrow[np * (DDIM / 4) + lane];

        float s[NHEAD];
        warp_scores(v, w, bini, lane, s);

        if (lane == 0 && n < MAXW)
            ssc[warp][n] = make_float4(s[0], s[1], s[2], s[3]);

        // warp-uniform running max with lazy rescale
        float nm[NHEAD];
        #pragma unroll
        for (int h = 0; h < NHEAD; h++) nm[h] = fmaxf(m[h], s[h]);
        if (nm[0] > m[0] || nm[1] > m[1] || nm[2] > m[2] || nm[3] > m[3]) {
            #pragma unroll
            for (int h = 0; h < NHEAD; h++) {
                float r = __expf(m[h] - nm[h]);   // 0 on first node
                acc[h].x *= r; acc[h].y *= r; acc[h].z *= r; acc[h].w *= r;
                S[h] *= r;
                m[h] = nm[h];
            }
        }

        #pragma unroll
        for (int h = 0; h < NHEAD; h++) {
            float e = __expf(s[h] - m[h]);
            S[h] += e;
            acc[h].x = fmaf(v.x, e, acc[h].x);
            acc[h].y = fmaf(v.y, e, acc[h].y);
            acc[h].z = fmaf(v.z, e, acc[h].z);
            acc[h].w = fmaf(v.w, e, acc[h].w);
        }
        v = vn;
    }

    float sinv[NHEAD];
    #pragma unroll
    for (int h = 0; h < NHEAD; h++) sinv[h] = 1.0f / S[h];

    // ---- pooled output: (1/4) * sum_h acc_h / S_h ----
    {
        float4 q = make_float4(0.f, 0.f, 0.f, 0.f);
        #pragma unroll
        for (int h = 0; h < NHEAD; h++) {
            float c = sinv[h] * 0.25f;
            q.x = fmaf(acc[h].x, c, q.x);
            q.y = fmaf(acc[h].y, c, q.y);
            q.z = fmaf(acc[h].z, c, q.z);
            q.w = fmaf(acc[h].w, c, q.w);
        }
        ((float4*)(out_pool + (size_t)b * DDIM))[lane] = q;
    }

    __syncwarp();

    // ---- Pass B: attention weights from cached scores (lane-parallel) ----
    const int cend = (cnt < MAXW) ? cnt : MAXW;
    for (int n = lane; n < cend; n += 32) {
        float4 sv = ssc[warp][n];
        out_attn[(size_t)0 * N + g0 + n] = __expf(sv.x - m[0]) * sinv[0];
        out_attn[(size_t)1 * N + g0 + n] = __expf(sv.y - m[1]) * sinv[1];
        out_attn[(size_t)2 * N + g0 + n] = __expf(sv.z - m[2]) * sinv[2];
        out_attn[(size_t)3 * N + g0 + n] = __expf(sv.w - m[3]) * sinv[3];
    }

    // ---- Fallback for cnt > MAXW (expected never): recompute scores ----
    for (int n = MAXW; n < cnt; n++) {
        float4 vv = xrow[n * (DDIM / 4) + lane];
        float s[NHEAD];
        warp_scores(vv, w, bini, lane, s);
        if (lane < NHEAD) {
            float sh = (lane < 2) ? ((lane == 0) ? s[0] : s[1])
                                  : ((lane == 2) ? s[2] : s[3]);
            float mh = (lane < 2) ? ((lane == 0) ? m[0] : m[1])
                                  : ((lane == 2) ? m[2] : m[3]);
            float si = (lane < 2) ? ((lane == 0) ? sinv[0] : sinv[1])
                                  : ((lane == 2) ? sinv[2] : sinv[3]);
            out_attn[(size_t)lane * N + g0 + n] = __expf(sh - mh) * si;
        }
    }
}

extern "C" void kernel_launch(void* const* d_in, const int* in_sizes, int n_in,
                              void* d_out, int out_size) {
    // Inputs: x [N,D] f32, batch_indices [N] int, W [H,D] f32, b [H] f32, temp [] f32
    const float* x    = (const float*)d_in[0];
    const void*  ids  = d_in[1];
    const float* W    = (const float*)d_in[2];
    const float* bias = (const float*)d_in[3];
    const float* temp = (const float*)d_in[4];

    const int N = in_sizes[1];
    const int B = (out_size - NHEAD * N) / DDIM;   // out = [B*D pooled | H*N attn]

    seg_bounds_kernel<<<(B + 1 + 255) / 256, 256>>>(ids, N, B);

    float* out_pool = (float*)d_out;
    float* out_attn = out_pool + (size_t)B * DDIM;
    attn_pool_warp_kernel<<<(B + WPB - 1) / WPB, THREADS>>>(x, W, bias, temp,
                                                            out_pool, out_attn,
                                                            N, B);
}

// round 7
// speedup vs baseline: 1.5424x; 1.0781x over previous
#include <cuda_runtime.h>
#include <cfloat>

#define DDIM   128
#define NHEAD  4
#define WPB    8            // warps per CTA
#define THREADS (WPB * 32)
#define MAXW   192          // score slots per warp (max cnt ~100 expected)

// Scratch for segment boundaries (device global: no allocations allowed).
__device__ int g_seg[65538];

__device__ __forceinline__ long long get_id(const void* ids, int i, bool is64) {
    if (is64) return ((const long long*)ids)[i];
    return (long long)((const int*)ids)[i];
}

// Kernel A: per-segment start offsets via lower_bound on sorted ids.
// Detects int64 vs int32 storage (sorted small int64 -> odd words at tail are 0).
__global__ void seg_bounds_kernel(const void* __restrict__ ids, int N, int B) {
    const int* w = (const int*)ids;
    bool is64 = false;
    if (N >= 8) {
        int nz = 0;
        #pragma unroll
        for (int k = 1; k <= 7; k += 2) nz += (w[N - k] != 0);
        is64 = (nz == 0);
    }
    int b = blockIdx.x * blockDim.x + threadIdx.x;
    if (b > B) return;
    int lo = 0, hi = N;
    while (lo < hi) {
        int mid = (lo + hi) >> 1;
        if (get_id(ids, mid, is64) < (long long)b) lo = mid + 1;
        else hi = mid;
    }
    g_seg[b] = lo;
}

// Warp-cooperative 4-head score for one row (float4 per lane).
// Returns s[0..3] on ALL lanes. 11 SHFL + 11 FADD + 4 SHFL-bcast.
__device__ __forceinline__ void warp_scores(
    float4 v, const float4 w[NHEAD], const float bini[NHEAD],
    int lane, float s[NHEAD]) {
    float p[NHEAD];
    #pragma unroll
    for (int h = 0; h < NHEAD; h++) {
        float t = fmaf(v.x, w[h].x, bini[h]);
        t = fmaf(v.y, w[h].y, t);
        t = fmaf(v.z, w[h].z, t);
        p[h] = fmaf(v.w, w[h].w, t);
    }
    // reduce over lane bits 4,3 for all 4 heads
    #pragma unroll
    for (int m = 16; m >= 8; m >>= 1) {
        #pragma unroll
        for (int h = 0; h < NHEAD; h++)
            p[h] += __shfl_xor_sync(0xffffffffu, p[h], m);
    }
    // transpose: lane group g = lane>>3 takes head g, reduce remaining 8 lanes
    int g = lane >> 3;
    float v8 = (g < 2) ? ((g == 0) ? p[0] : p[1]) : ((g == 2) ? p[2] : p[3]);
    #pragma unroll
    for (int m = 4; m >= 1; m >>= 1)
        v8 += __shfl_xor_sync(0xffffffffu, v8, m);
    #pragma unroll
    for (int h = 0; h < NHEAD; h++)
        s[h] = __shfl_sync(0xffffffffu, v8, h * 8);
}

__global__ __launch_bounds__(THREADS, 4)
void attn_pool_warp_kernel(const float* __restrict__ x,
                           const float* __restrict__ W,
                           const float* __restrict__ bias,
                           const float* __restrict__ temp,
                           float* __restrict__ out_pool,
                           float* __restrict__ out_attn,
                           int N, int B) {
    const int lane = threadIdx.x & 31;
    const int warp = threadIdx.x >> 5;
    const int b    = blockIdx.x * WPB + warp;

    __shared__ float4 ssc[WPB][MAXW];   // per-warp score slots

    if (b >= B) return;

    const float invT = 1.0f / temp[0];

    // Per-lane weights (folded with 1/T); bias distributed over 32 lane partials.
    float4 w[NHEAD];
    float  bini[NHEAD];
    #pragma unroll
    for (int h = 0; h < NHEAD; h++) {
        const float4 wr = ((const float4*)(W + h * DDIM))[lane];
        w[h] = make_float4(wr.x * invT, wr.y * invT, wr.z * invT, wr.w * invT);
        bini[h] = bias[h] * invT * (1.0f / 32.0f);
    }

    const int g0  = g_seg[b];
    const int cnt = g_seg[b + 1] - g0;

    if (cnt == 0) {
        ((float4*)(out_pool + (size_t)b * DDIM))[lane] =
            make_float4(0.f, 0.f, 0.f, 0.f);
        return;
    }

    // ---- Pass A: single sweep over x -- scores + online softmax + pooling ----
    float m[NHEAD], S[NHEAD];
    float4 acc[NHEAD];
    #pragma unroll
    for (int h = 0; h < NHEAD; h++) {
        m[h] = -FLT_MAX; S[h] = 0.f;
        acc[h] = make_float4(0.f, 0.f, 0.f, 0.f);
    }

    const float4* xrow = (const float4*)(x + (size_t)g0 * DDIM);
    float4 v = xrow[lane];                        // prefetch row 0

    for (int n = 0; n < cnt; n++) {
        // Unconditional prefetch of next row (clamped index) keeps the LDG
        // hoisted/unpredicated -> 2 rows in flight.
        const int np = (n + 1 < cnt) ? (n + 1) : n;
        float4 vn = xrow[np * (DDIM / 4) + lane];

        float s[NHEAD];
        warp_scores(v, w, bini, lane, s);

        if (lane == 0 && n < MAXW)
            ssc[warp][n] = make_float4(s[0], s[1], s[2], s[3]);

        // warp-uniform running max with lazy rescale
        float nm[NHEAD];
        #pragma unroll
        for (int h = 0; h < NHEAD; h++) nm[h] = fmaxf(m[h], s[h]);
        if (nm[0] > m[0] || nm[1] > m[1] || nm[2] > m[2] || nm[3] > m[3]) {
            #pragma unroll
            for (int h = 0; h < NHEAD; h++) {
                float r = __expf(m[h] - nm[h]);   // 0 on first node
                acc[h].x *= r; acc[h].y *= r; acc[h].z *= r; acc[h].w *= r;
                S[h] *= r;
                m[h] = nm[h];
            }
        }

        #pragma unroll
        for (int h = 0; h < NHEAD; h++) {
            float e = __expf(s[h] - m[h]);
            S[h] += e;
            acc[h].x = fmaf(v.x, e, acc[h].x);
            acc[h].y = fmaf(v.y, e, acc[h].y);
            acc[h].z = fmaf(v.z, e, acc[h].z);
            acc[h].w = fmaf(v.w, e, acc[h].w);
        }
        v = vn;
    }

    float sinv[NHEAD];
    #pragma unroll
    for (int h = 0; h < NHEAD; h++) sinv[h] = 1.0f / S[h];

    // ---- pooled output: (1/4) * sum_h acc_h / S_h ----
    {
        float4 q = make_float4(0.f, 0.f, 0.f, 0.f);
        #pragma unroll
        for (int h = 0; h < NHEAD; h++) {
            float c = sinv[h] * 0.25f;
            q.x = fmaf(acc[h].x, c, q.x);
            q.y = fmaf(acc[h].y, c, q.y);
            q.z = fmaf(acc[h].z, c, q.z);
            q.w = fmaf(acc[h].w, c, q.w);
        }
        ((float4*)(out_pool + (size_t)b * DDIM))[lane] = q;
    }

    __syncwarp();

    // ---- Pass B: attention weights from cached scores (lane-parallel) ----
    const int cend = (cnt < MAXW) ? cnt : MAXW;
    for (int n = lane; n < cend; n += 32) {
        float4 sv = ssc[warp][n];
        out_attn[(size_t)0 * N + g0 + n] = __expf(sv.x - m[0]) * sinv[0];
        out_attn[(size_t)1 * N + g0 + n] = __expf(sv.y - m[1]) * sinv[1];
        out_attn[(size_t)2 * N + g0 + n] = __expf(sv.z - m[2]) * sinv[2];
        out_attn[(size_t)3 * N + g0 + n] = __expf(sv.w - m[3]) * sinv[3];
    }

    // ---- Fallback for cnt > MAXW (expected never): recompute scores ----
    for (int n = MAXW; n < cnt; n++) {
        float4 vv = xrow[n * (DDIM / 4) + lane];
        float s[NHEAD];
        warp_scores(vv, w, bini, lane, s);
        if (lane < NHEAD) {
            float sh = (lane < 2) ? ((lane == 0) ? s[0] : s[1])
                                  : ((lane == 2) ? s[2] : s[3]);
            float mh = (lane < 2) ? ((lane == 0) ? m[0] : m[1])
                                  : ((lane == 2) ? m[2] : m[3]);
            float si = (lane < 2) ? ((lane == 0) ? sinv[0] : sinv[1])
                                  : ((lane == 2) ? sinv[2] : sinv[3]);
            out_attn[(size_t)lane * N + g0 + n] = __expf(sh - mh) * si;
        }
    }
}

extern "C" void kernel_launch(void* const* d_in, const int* in_sizes, int n_in,
                              void* d_out, int out_size) {
    // Inputs: x [N,D] f32, batch_indices [N] int, W [H,D] f32, b [H] f32, temp [] f32
    const float* x    = (const float*)d_in[0];
    const void*  ids  = d_in[1];
    const float* W    = (const float*)d_in[2];
    const float* bias = (const float*)d_in[3];
    const float* temp = (const float*)d_in[4];

    const int N = in_sizes[1];
    const int B = (out_size - NHEAD * N) / DDIM;   // out = [B*D pooled | H*N attn]

    seg_bounds_kernel<<<(B + 1 + 255) / 256, 256>>>(ids, N, B);

    float* out_pool = (float*)d_out;
    float* out_attn = out_pool + (size_t)B * DDIM;
    attn_pool_warp_kernel<<<(B + WPB - 1) / WPB, THREADS>>>(x, W, bias, temp,
                                                            out_pool, out_attn,
                                                            N, B);
}